// round 8
// baseline (speedup 1.0000x reference)
#include <cuda_runtime.h>
#include <cuda_fp16.h>

#define B_DIM 2048
#define IN_DIM 8192
#define O_DIM 4096
#define K_DIM 64

#define BS 8                  // b's per CTA slice
#define ROW_BYTES 20          // 16B payload + 4B pad -> row start bank = 5r mod 32
#define NCTA (B_DIM / BS)     // 256 CTAs
#define NTHR 512              // 16 warps
#define NWARP (NTHR / 32)

// Packed table: (idx*5)<<16 | fp16(w).  idx*5 <= 40955 fits 16 bits.
// Byte offset of row = (word>>16)<<2 = idx*20.
__device__ unsigned int g_pk[O_DIM * K_DIM];  // 1 MB

__global__ __launch_bounds__(256) void pack_kernel(const int* __restrict__ indices,
                                                   const float* __restrict__ weight) {
    int t = blockIdx.x * blockDim.x + threadIdx.x;
    if (t < O_DIM * K_DIM) {
        unsigned int hw = __half_as_ushort(__float2half(weight[t]));
        g_pk[t] = ((unsigned int)(indices[t] * 5) << 16) | hw;
    }
}

// ---------------------------------------------------------------------------
// smem gather, take 2.
// R7 failed on: per-thread LDS.128 (4 phases, 8 scattered rows each), 16B
// stride (8 bank-alignment classes), fat inner loop. Fixes:
//  - quad-cooperative LDS.32: 4 lanes read one row's 4 consecutive words;
//    warp = 8 rows, single 32-lane phase when conflict-free.
//  - 20B row stride: start banks 5r mod 32 (32 positions, not 8 classes).
//  - HFMA2 accumulate in 4-k groups -> ~6 instr/k, crossbar binds, not issue.
// CTA owns 8 consecutive b's; x rows are contiguous -> no transpose pass.
// ---------------------------------------------------------------------------
extern __shared__ unsigned char sl[];  // IN_DIM * 20 = 160 KB

__global__ __launch_bounds__(NTHR) void gather3_kernel(const float* __restrict__ x,
                                                       const float* __restrict__ bias,
                                                       float* __restrict__ out) {
    const int tid = threadIdx.x;
    const int b0 = blockIdx.x * BS;

    // ---- Load + convert slice: x[b0..b0+7][0..8191] f32 -> sl rows of 8 halves.
    // half for (i, bb) at byte i*20 + (bb>>1)*4 + (bb&1)*2.
    // STS.16 addresses stride 20B across lanes -> banks 5l+c mod 32, conflict-free.
#pragma unroll
    for (int bb = 0; bb < BS; bb++) {
        const float4* __restrict__ xrow = (const float4*)(x + (size_t)(b0 + bb) * IN_DIM);
        const int sub = (bb >> 1) * 4 + (bb & 1) * 2;
        for (int i4 = tid; i4 < IN_DIM / 4; i4 += NTHR) {
            const float4 v = xrow[i4];
            const int i = i4 * 4;
            *(__half*)(sl + (i + 0) * ROW_BYTES + sub) = __float2half(v.x);
            *(__half*)(sl + (i + 1) * ROW_BYTES + sub) = __float2half(v.y);
            *(__half*)(sl + (i + 2) * ROW_BYTES + sub) = __float2half(v.z);
            *(__half*)(sl + (i + 3) * ROW_BYTES + sub) = __float2half(v.w);
        }
    }
    __syncthreads();

    // ---- Sweep all (o,k). Quad q=lane/4 owns o=og+q; lane's c=lane%4 owns
    // b-pair (b0+2c, b0+2c+1). Warp covers 8 o's per round.
    const int lane = tid & 31;
    const int wid = tid >> 5;
    const int q = lane >> 2;
    const int c = lane & 3;
    const unsigned int cb = (unsigned int)(c * 4);

    for (int og = wid * 8; og < O_DIM; og += NWARP * 8) {
        const int o = og + q;
        const uint4* __restrict__ p4 = (const uint4*)(g_pk + o * K_DIM);

        float accx = 0.f, accy = 0.f;

#pragma unroll 8
        for (int kk = 0; kk < K_DIM / 4; kk++) {
            const uint4 u = p4[kk];  // 4 packed (idx*5 | w); quad lanes share addr
            __half2 hacc = __floats2half2_rn(0.f, 0.f);
            {
                const unsigned int e = u.x;
                const __half2 v = *(const __half2*)(sl + ((e >> 16) << 2) + cb);
                unsigned int wb = __byte_perm(e, e, 0x1010);  // w|w
                hacc = __hfma2(v, *(const __half2*)&wb, hacc);
            }
            {
                const unsigned int e = u.y;
                const __half2 v = *(const __half2*)(sl + ((e >> 16) << 2) + cb);
                unsigned int wb = __byte_perm(e, e, 0x1010);
                hacc = __hfma2(v, *(const __half2*)&wb, hacc);
            }
            {
                const unsigned int e = u.z;
                const __half2 v = *(const __half2*)(sl + ((e >> 16) << 2) + cb);
                unsigned int wb = __byte_perm(e, e, 0x1010);
                hacc = __hfma2(v, *(const __half2*)&wb, hacc);
            }
            {
                const unsigned int e = u.w;
                const __half2 v = *(const __half2*)(sl + ((e >> 16) << 2) + cb);
                unsigned int wb = __byte_perm(e, e, 0x1010);
                hacc = __hfma2(v, *(const __half2*)&wb, hacc);
            }
            // dump fp16 partial (4 terms) into fp32 accumulators
            const float2 f = __half22float2(hacc);
            accx += f.x;
            accy += f.y;
        }

        const float bv = bias[o];
        out[(size_t)(b0 + 2 * c + 0) * O_DIM + o] = accx + bv;
        out[(size_t)(b0 + 2 * c + 1) * O_DIM + o] = accy + bv;
    }
}

// ---------------------------------------------------------------------------
// Launch
// ---------------------------------------------------------------------------
extern "C" void kernel_launch(void* const* d_in, const int* in_sizes, int n_in,
                              void* d_out, int out_size) {
    (void)in_sizes; (void)n_in; (void)out_size;
    const float* x = (const float*)d_in[0];
    const int* indices = (const int*)d_in[1];
    const float* weight = (const float*)d_in[2];
    const float* bias = (const float*)d_in[3];
    float* out = (float*)d_out;

    const int smem_bytes = IN_DIM * ROW_BYTES;  // 160 KB
    static int configured = 0;
    if (!configured) {
        cudaFuncSetAttribute(gather3_kernel, cudaFuncAttributeMaxDynamicSharedMemorySize,
                             smem_bytes);
        configured = 1;
    }

    pack_kernel<<<(O_DIM * K_DIM + 255) / 256, 256>>>(indices, weight);
    gather3_kernel<<<NCTA, NTHR, smem_bytes>>>(x, bias, out);
}

// round 10
// speedup vs baseline: 1.8322x; 1.8322x over previous
#include <cuda_runtime.h>
#include <cuda_fp16.h>

#define B_DIM 2048
#define IN_DIM 8192
#define O_DIM 4096
#define K_DIM 64

// 32 MB transposed fp16 copy of x: xth[i][b] (b contiguous, L2-resident)
__device__ __half g_xth[(size_t)IN_DIM * B_DIM];

// ---------------------------------------------------------------------------
// Kernel 1: transpose+convert x[B, IN] f32 -> g_xth[IN, B] f16.
// 64x64 tile, float4 loads, half4 (uint2) stores -> DRAM-limited (~11us).
// smem padded to 68 halves/row to spread bank bases.
// ---------------------------------------------------------------------------
#define TP 68  // padded row length (halves)

__global__ __launch_bounds__(256) void transpose_kernel(const float* __restrict__ x) {
    __shared__ __half st[64][TP];  // st[i_local][b_local]
    const int i0 = blockIdx.x * 64;
    const int b0 = blockIdx.y * 64;
    const int t = threadIdx.x;
    const int r = t >> 2;   // 0..63
    const int c = t & 3;    // 0..3

    // Phase 1: row (b0+r) of x, 4 float4 chunks per thread -> st[i][r]
    const float4* __restrict__ xr = (const float4*)(x + (size_t)(b0 + r) * IN_DIM + i0);
#pragma unroll
    for (int j = 0; j < 4; j++) {
        const float4 f = xr[c + 4 * j];
        const int il = 4 * (c + 4 * j);
        st[il + 0][r] = __float2half(f.x);
        st[il + 1][r] = __float2half(f.y);
        st[il + 2][r] = __float2half(f.z);
        st[il + 3][r] = __float2half(f.w);
    }
    __syncthreads();

    // Phase 2: row (i0+r) of xt, 4 half4 (8B) chunks per thread
    __half* __restrict__ xtr = g_xth + (size_t)(i0 + r) * B_DIM + b0;
#pragma unroll
    for (int j = 0; j < 4; j++) {
        const int bl = 4 * (c + 4 * j);
        *(uint2*)(xtr + bl) = *(const uint2*)&st[r][bl];
    }
}

// ---------------------------------------------------------------------------
// Kernel 2: gather + weighted reduce (fp16 xt, fp32 accumulate).
// R4 structure (proven at the L2 sector roof) with the store path fixed:
// OACC=4 -> epilogue writes float4 out[b][o..o+3] (16B, 2 accesses/sector
// instead of R4's 4x8B) and 4 LDG.128 in flight per k.
// Thread owns 8 consecutive b (one uint4 of halves); 256 thr cover all B.
// grid = (1, 512). idx premultiplied + w fused in int2 smem.
// ---------------------------------------------------------------------------
#define OT 8
#define OACC 4
#define NTHR 256

__global__ __launch_bounds__(NTHR, 3) void gather_kernel(const int* __restrict__ indices,
                                                         const float* __restrict__ weight,
                                                         const float* __restrict__ bias,
                                                         float* __restrict__ out) {
    __shared__ int2 s_iw[OT * K_DIM];  // 4 KB: {premultiplied row offset, w bits}

    const int tid = threadIdx.x;
    const int obase = blockIdx.y * OT;
    const int brow = tid * 8;  // first of this thread's 8 b's

    for (int t = tid; t < OT * K_DIM; t += NTHR) {
        int2 iw;
        iw.x = indices[(size_t)obase * K_DIM + t] * (B_DIM / 8);
        iw.y = __float_as_int(weight[(size_t)obase * K_DIM + t]);
        s_iw[t] = iw;
    }
    __syncthreads();

    const uint4* __restrict__ xt8 = (const uint4*)g_xth;

    for (int og = 0; og < OT; og += OACC) {
        float acc[OACC][8];
#pragma unroll
        for (int j = 0; j < OACC; j++)
#pragma unroll
            for (int q = 0; q < 8; q++) acc[j][q] = 0.f;

#pragma unroll 2
        for (int k = 0; k < K_DIM; k++) {
#pragma unroll
            for (int j = 0; j < OACC; j++) {
                const int2 iw = s_iw[(og + j) * K_DIM + k];  // one LDS.64
                const float w = __int_as_float(iw.y);
                const uint4 v = xt8[iw.x + tid];             // 8 halves, coalesced along b
                const __half2* h = (const __half2*)&v;
#pragma unroll
                for (int q = 0; q < 4; q++) {
                    const float2 f = __half22float2(h[q]);
                    acc[j][2 * q + 0] += f.x * w;
                    acc[j][2 * q + 1] += f.y * w;
                }
            }
        }

        float bv[OACC];
#pragma unroll
        for (int j = 0; j < OACC; j++) bv[j] = bias[obase + og + j];

        // Full-width stores: out[b][og..og+3] as one STG.128 per b
#pragma unroll
        for (int bb = 0; bb < 8; bb++) {
            float4 v;
            v.x = acc[0][bb] + bv[0];
            v.y = acc[1][bb] + bv[1];
            v.z = acc[2][bb] + bv[2];
            v.w = acc[3][bb] + bv[3];
            *(float4*)(out + (size_t)(brow + bb) * O_DIM + obase + og) = v;
        }
    }
}

// ---------------------------------------------------------------------------
// Launch
// ---------------------------------------------------------------------------
extern "C" void kernel_launch(void* const* d_in, const int* in_sizes, int n_in,
                              void* d_out, int out_size) {
    (void)in_sizes; (void)n_in; (void)out_size;
    const float* x = (const float*)d_in[0];
    const int* indices = (const int*)d_in[1];
    const float* weight = (const float*)d_in[2];
    const float* bias = (const float*)d_in[3];
    float* out = (float*)d_out;

    dim3 tg(IN_DIM / 64, B_DIM / 64);  // (128, 32)
    transpose_kernel<<<tg, 256>>>(x);

    dim3 gg(1, O_DIM / OT);  // (1, 512)
    gather_kernel<<<gg, NTHR>>>(indices, weight, bias, out);
}

// round 11
// speedup vs baseline: 1.8976x; 1.0357x over previous
#include <cuda_runtime.h>
#include <cuda_fp16.h>

#define B_DIM 2048
#define IN_DIM 8192
#define O_DIM 4096
#define K_DIM 64

// 32 MB transposed fp16 copy of x: xth[i][b] (b contiguous, L2-resident)
__device__ __half g_xth[(size_t)IN_DIM * B_DIM];

// ---------------------------------------------------------------------------
// Kernel 1: transpose+convert x[B, IN] f32 -> g_xth[IN, B] f16.
// R9 version was issue-bound (~45 mem instr/thread, 16 scalar STS.16).
// v3: half2-granular. Tile 64 b x 64 i. st2[i2][r] = half2(x[r][2*i2], x[r][2*i2+1]),
// pitch 76 half2 -> phase1 STS.32 banks (24c+12d+r) mod 32 all-distinct,
// phase2 LDS.128 windows (m mod 8) distinct per 8-lane phase: conflict-free.
// Per thread: 4 LDG.128 + 8 cvt + 8 STS.32 + 2 LDS.128 + 8 PRMT + 4 STG.64.
// ---------------------------------------------------------------------------
#define TPITCH 76  // half2 pitch (76 mod 16 == 12 -> conflict-free phase 1)

__global__ __launch_bounds__(256) void transpose_kernel(const float* __restrict__ x) {
    __shared__ __half2 st2[32][TPITCH];  // 9.5 KB
    const int i0 = blockIdx.x * 64;
    const int b0 = blockIdx.y * 64;
    const int t = threadIdx.x;

    // Phase 1: r = b_local (t>>2), c = i-chunk (t&3). Read 4 float4 per thread.
    {
        const int r = t >> 2;
        const int c = t & 3;
        const float4* __restrict__ xr = (const float4*)(x + (size_t)(b0 + r) * IN_DIM + i0);
#pragma unroll
        for (int j = 0; j < 4; j++) {
            const float4 f = xr[c + 4 * j];
            const int i2 = 2 * c + 8 * j;  // i-pair index
            st2[i2 + 0][r] = __floats2half2_rn(f.x, f.y);
            st2[i2 + 1][r] = __floats2half2_rn(f.z, f.w);
        }
    }
    __syncthreads();

    // Phase 2: p2 = t>>4 (0..15) selects i-pair rows 2*p2, 2*p2+1;
    // m = t&15 selects b-chunk of 4. Deinterleave lows/highs via PRMT.
    {
        const int p2 = t >> 4;
        const int m = t & 15;
        const int bb = 4 * m;

#pragma unroll
        for (int pp = 0; pp < 2; pp++) {
            const int p = 2 * p2 + pp;  // i2 row: holds i = 2p, 2p+1
            // LDS.128: 4 half2 (b = bb..bb+3) of i-pair p
            const uint4 u = *(const uint4*)&st2[p][bb];
            // lows -> row i = 2p, highs -> row i = 2p+1
            unsigned int lo0 = __byte_perm(u.x, u.y, 0x5410);
            unsigned int lo1 = __byte_perm(u.z, u.w, 0x5410);
            unsigned int hi0 = __byte_perm(u.x, u.y, 0x7632);
            unsigned int hi1 = __byte_perm(u.z, u.w, 0x7632);
            __half* __restrict__ row0 = g_xth + (size_t)(i0 + 2 * p + 0) * B_DIM + b0 + bb;
            __half* __restrict__ row1 = g_xth + (size_t)(i0 + 2 * p + 1) * B_DIM + b0 + bb;
            *(uint2*)row0 = make_uint2(lo0, lo1);
            *(uint2*)row1 = make_uint2(hi0, hi1);
        }
    }
}

// ---------------------------------------------------------------------------
// Kernel 2: gather + weighted reduce (fp16 xt, fp32 accumulate).
// UNCHANGED from R10 (measured 102.3us = chip LTS read-sector roof:
// 33.5M sectors / 184 slices / ~1.78GHz. Frozen.)
// ---------------------------------------------------------------------------
#define OT 8
#define OACC 4
#define NTHR 256

__global__ __launch_bounds__(NTHR, 3) void gather_kernel(const int* __restrict__ indices,
                                                         const float* __restrict__ weight,
                                                         const float* __restrict__ bias,
                                                         float* __restrict__ out) {
    __shared__ int2 s_iw[OT * K_DIM];  // 4 KB: {premultiplied row offset, w bits}

    const int tid = threadIdx.x;
    const int obase = blockIdx.y * OT;
    const int brow = tid * 8;  // first of this thread's 8 b's

    for (int t = tid; t < OT * K_DIM; t += NTHR) {
        int2 iw;
        iw.x = indices[(size_t)obase * K_DIM + t] * (B_DIM / 8);
        iw.y = __float_as_int(weight[(size_t)obase * K_DIM + t]);
        s_iw[t] = iw;
    }
    __syncthreads();

    const uint4* __restrict__ xt8 = (const uint4*)g_xth;

    for (int og = 0; og < OT; og += OACC) {
        float acc[OACC][8];
#pragma unroll
        for (int j = 0; j < OACC; j++)
#pragma unroll
            for (int q = 0; q < 8; q++) acc[j][q] = 0.f;

#pragma unroll 2
        for (int k = 0; k < K_DIM; k++) {
#pragma unroll
            for (int j = 0; j < OACC; j++) {
                const int2 iw = s_iw[(og + j) * K_DIM + k];  // one LDS.64
                const float w = __int_as_float(iw.y);
                const uint4 v = xt8[iw.x + tid];             // 8 halves, coalesced along b
                const __half2* h = (const __half2*)&v;
#pragma unroll
                for (int q = 0; q < 4; q++) {
                    const float2 f = __half22float2(h[q]);
                    acc[j][2 * q + 0] += f.x * w;
                    acc[j][2 * q + 1] += f.y * w;
                }
            }
        }

        float bv[OACC];
#pragma unroll
        for (int j = 0; j < OACC; j++) bv[j] = bias[obase + og + j];

#pragma unroll
        for (int bb = 0; bb < 8; bb++) {
            float4 v;
            v.x = acc[0][bb] + bv[0];
            v.y = acc[1][bb] + bv[1];
            v.z = acc[2][bb] + bv[2];
            v.w = acc[3][bb] + bv[3];
            *(float4*)(out + (size_t)(brow + bb) * O_DIM + obase + og) = v;
        }
    }
}

// ---------------------------------------------------------------------------
// Launch
// ---------------------------------------------------------------------------
extern "C" void kernel_launch(void* const* d_in, const int* in_sizes, int n_in,
                              void* d_out, int out_size) {
    (void)in_sizes; (void)n_in; (void)out_size;
    const float* x = (const float*)d_in[0];
    const int* indices = (const int*)d_in[1];
    const float* weight = (const float*)d_in[2];
    const float* bias = (const float*)d_in[3];
    float* out = (float*)d_out;

    dim3 tg(IN_DIM / 64, B_DIM / 64);  // (128, 32)
    transpose_kernel<<<tg, 256>>>(x);

    dim3 gg(1, O_DIM / OT);  // (1, 512)
    gather_kernel<<<gg, NTHR>>>(indices, weight, bias, out);
}